// round 1
// baseline (speedup 1.0000x reference)
#include <cuda_runtime.h>
#include <cstdint>

#define HH 512
#define WW 512
#define BATCH 16
#define WORDS 16  // 512 / 32

// Scratch: bit-packed strong/weak masks for both inputs. 2*16*512*16*4 = 2 MB each.
__device__ uint32_t g_strong[2 * BATCH * HH * WORDS];
__device__ uint32_t g_weak[2 * BATCH * HH * WORDS];
__device__ int g_cnt;

__device__ __forceinline__ int reflect_idx(int p, int n) {
    if (p < 0) p = -p;
    if (p >= n) p = 2 * n - 2 - p;
    return p;
}

// ---------------- Kernel 1: gray -> gaussian blur -> sobel -> NMS -> double threshold ----------------
#define TILE 64
#define GSZ 72   // tile + 2*4 halo (gray)
#define GP 73
#define BSZ 68   // tile + 2*2 halo (blur)
#define BP 69
#define MSZ 66   // tile + 2*1 halo (mag)
#define MP 67

__global__ __launch_bounds__(256) void canny_state_kernel(
    const float* __restrict__ in0, const float* __restrict__ in1)
{
    __shared__ float G[GSZ * GP];   // gray; later aliased as mag (M)
    __shared__ float Bm[BSZ * BP];  // blur

    const int tx = blockIdx.x, ty = blockIdx.y, z = blockIdx.z;
    const int u = z >> 4, b = z & 15;
    const float* img = (u == 0 ? in0 : in1) + (size_t)b * 3 * HH * WW;
    const int TX = tx * TILE, TY = ty * TILE;
    const int tid = threadIdx.x;

    // Gaussian weights (sigma=1, 5 taps), matching jnp computation order
    const float e2 = expf(-2.0f), e05 = expf(-0.5f);
    const float ssum = (((e2 + e05) + 1.0f) + e05) + e2;
    const float w0 = e2 / ssum, w1 = e05 / ssum, w2 = 1.0f / ssum;
    const float wv[5] = {w0, w1, w2, w1, w0};

    // Phase 1: grayscale with reflect indexing (covers blur's reflect needs;
    // symmetric kernel commutes with reflection so halo values are exact)
    for (int i = tid; i < GSZ * GSZ; i += 256) {
        int lr = i / GSZ, lc = i % GSZ;
        int rr = reflect_idx(TY - 4 + lr, HH);
        int rc = reflect_idx(TX - 4 + lc, WW);
        const float* p = img + (size_t)rr * WW + rc;
        float r = p[0];
        float g = p[HH * WW];
        float bl = p[2 * HH * WW];
        G[lr * GP + lc] = 0.299f * r + 0.587f * g + 0.114f * bl;
    }
    __syncthreads();

    // Phase 2: 5x5 gaussian blur (separable weights, direct sum)
    for (int i = tid; i < BSZ * BSZ; i += 256) {
        int lr = i / BSZ, lc = i % BSZ;
        float acc = 0.f;
        #pragma unroll
        for (int dy = 0; dy < 5; dy++) {
            float rowacc = 0.f;
            #pragma unroll
            for (int dx = 0; dx < 5; dx++)
                rowacc += wv[dx] * G[(lr + dy) * GP + lc + dx];
            acc += wv[dy] * rowacc;
        }
        Bm[lr * BP + lc] = acc;
    }
    __syncthreads();

    // Phase 3: gradient magnitude (zero outside image — NMS uses zero-padded shifts)
    float* M = G;  // alias: gray no longer needed
    for (int i = tid; i < MSZ * MSZ; i += 256) {
        int lr = i / MSZ, lc = i % MSZ;
        int gy = TY - 1 + lr, gx = TX - 1 + lc;
        float mag = 0.f;
        if (gy >= 0 && gy < HH && gx >= 0 && gx < WW) {
            float b00 = Bm[lr * BP + lc],       b01 = Bm[lr * BP + lc + 1],       b02 = Bm[lr * BP + lc + 2];
            float b10 = Bm[(lr + 1) * BP + lc],                                    b12 = Bm[(lr + 1) * BP + lc + 2];
            float b20 = Bm[(lr + 2) * BP + lc], b21 = Bm[(lr + 2) * BP + lc + 1], b22 = Bm[(lr + 2) * BP + lc + 2];
            float gxv = (b02 + 2.f * b12 + b22) - (b00 + 2.f * b10 + b20);
            float gyv = (b20 + 2.f * b21 + b22) - (b00 + 2.f * b01 + b02);
            mag = sqrtf(gxv * gxv + gyv * gyv + 1e-12f);
        }
        M[lr * MP + lc] = mag;
    }
    __syncthreads();

    // Phase 4: NMS + double threshold, bit-packed output via ballot.
    // Direction bin via comparisons; ties match banker's rounding (ties -> even bins).
    const float TAN22 = 0.41421356237309503f;  // tan(pi/8)
    const int wp = tid >> 5, l = tid & 31;
    for (int t = wp; t < 128; t += 8) {         // 64 rows x 2 column-segments
        int r = t >> 1, seg = t & 1;
        int c = seg * 32 + l;
        // sobel at output pixel (r,c): blur rows r+1..r+3, cols c+1..c+3
        float b00 = Bm[(r + 1) * BP + c + 1], b01 = Bm[(r + 1) * BP + c + 2], b02 = Bm[(r + 1) * BP + c + 3];
        float b10 = Bm[(r + 2) * BP + c + 1],                                  b12 = Bm[(r + 2) * BP + c + 3];
        float b20 = Bm[(r + 3) * BP + c + 1], b21 = Bm[(r + 3) * BP + c + 2], b22 = Bm[(r + 3) * BP + c + 3];
        float gxv = (b02 + 2.f * b12 + b22) - (b00 + 2.f * b10 + b20);
        float gyv = (b20 + 2.f * b21 + b22) - (b00 + 2.f * b01 + b02);
        float ax = fabsf(gxv), ay = fabsf(gyv);
        int bin;
        if (ay <= TAN22 * ax)       bin = 0;  // ~0 or ~180 deg
        else if (ax <= TAN22 * ay)  bin = 2;  // ~90 deg
        else bin = ((gxv > 0.f) == (gyv > 0.f)) ? 1 : 3;  // 45 / 135

        int dy = (bin == 0) ? 0 : 1;
        int dx = (bin == 2) ? 0 : ((bin == 3) ? -1 : 1);

        float magc = M[(r + 1) * MP + (c + 1)];
        float n1 = M[(r + 1 + dy) * MP + (c + 1 + dx)];
        float n2 = M[(r + 1 - dy) * MP + (c + 1 - dx)];
        bool keep = (magc >= n1) && (magc >= n2);
        float nms = keep ? magc : 0.f;
        bool strong = (nms >= 0.2f);
        bool weak = (!strong) && (nms >= 0.1f);

        unsigned sm = __ballot_sync(0xffffffffu, strong);
        unsigned wm = __ballot_sync(0xffffffffu, weak);
        if (l == 0) {
            size_t idx = (((size_t)(u * BATCH + b) * HH) + (TY + r)) * WORDS + (tx * 2 + seg);
            g_strong[idx] = sm;
            g_weak[idx]   = wm;
        }
    }
}

// ---------------- Kernel 2: 10x hysteresis (bitwise) + diff count ----------------
// Tile 64x64, row halo 10, col halo 32 (one word). All 10 global iterations done
// locally (halo >= 10 guarantees exact equivalence).
#define HR 84   // 64 + 2*10 rows
#define HW4 4   // 4 words = 128 bits (64 + 2*32 cols)

__global__ __launch_bounds__(256) void hyst_count_kernel()
{
    __shared__ uint32_t S[2][HR][HW4];
    __shared__ uint32_t Wk[2][HR][HW4];
    __shared__ uint32_t Hh[2][HR][HW4];
    __shared__ int warpsum[8];

    const int tx = blockIdx.x, ty = blockIdx.y, b = blockIdx.z;
    const int TY = ty * TILE;
    const int tid = threadIdx.x;
    const int NW = 2 * HR * HW4;  // 672 word-tasks

    // Load (out-of-image -> 0, matching zero-padded reduce_window border)
    for (int i = tid; i < NW; i += 256) {
        int uu = i / (HR * HW4);
        int rem = i % (HR * HW4);
        int r = rem / HW4, w = rem % HW4;
        int gy = TY - 10 + r;
        int gw = tx * 2 - 1 + w;
        uint32_t sv = 0, wv = 0;
        if (gy >= 0 && gy < HH && gw >= 0 && gw < WORDS) {
            size_t idx = (((size_t)(uu * BATCH + b) * HH) + gy) * WORDS + gw;
            sv = g_strong[idx];
            wv = g_weak[idx];
        }
        S[uu][r][w] = sv;
        Wk[uu][r][w] = wv;
    }
    __syncthreads();

    for (int it = 0; it < 10; it++) {
        // Horizontal dilation (includes center)
        for (int i = tid; i < NW; i += 256) {
            int uu = i / (HR * HW4);
            int rem = i % (HR * HW4);
            int r = rem / HW4, w = rem % HW4;
            uint32_t s = S[uu][r][w];
            uint32_t lf = (w > 0) ? S[uu][r][w - 1] : 0u;
            uint32_t rt = (w < HW4 - 1) ? S[uu][r][w + 1] : 0u;
            Hh[uu][r][w] = s | (s << 1) | (s >> 1) | (lf >> 31) | (rt << 31);
        }
        __syncthreads();
        // Vertical OR + promote weak -> strong
        for (int i = tid; i < NW; i += 256) {
            int uu = i / (HR * HW4);
            int rem = i % (HR * HW4);
            int r = rem / HW4, w = rem % HW4;
            uint32_t nb = Hh[uu][r][w];
            if (r > 0) nb |= Hh[uu][r - 1][w];
            if (r < HR - 1) nb |= Hh[uu][r + 1][w];
            uint32_t pr = Wk[uu][r][w] & nb;
            S[uu][r][w] |= pr;
            Wk[uu][r][w] &= ~pr;
        }
        __syncthreads();
    }

    // Count |e1 - e2| over the 64x64 interior (rows 10..73, words 1..2)
    int cnt = 0;
    for (int i = tid; i < 128; i += 256) {
        int r = 10 + (i >> 1);
        int w = 1 + (i & 1);
        cnt += __popc(S[0][r][w] ^ S[1][r][w]);
    }
    #pragma unroll
    for (int off = 16; off; off >>= 1)
        cnt += __shfl_down_sync(0xffffffffu, cnt, off);
    if ((tid & 31) == 0) warpsum[tid >> 5] = cnt;
    __syncthreads();
    if (tid == 0) {
        int tot = 0;
        #pragma unroll
        for (int k = 0; k < 8; k++) tot += warpsum[k];
        atomicAdd(&g_cnt, tot);
    }
}

__global__ void zero_kernel() { g_cnt = 0; }

__global__ void finalize_kernel(float* __restrict__ out) {
    out[0] = (float)g_cnt / 4194304.0f;  // 16*512*512
}

extern "C" void kernel_launch(void* const* d_in, const int* in_sizes, int n_in,
                              void* d_out, int out_size) {
    const float* y_hat = (const float*)d_in[0];
    const float* y     = (const float*)d_in[1];
    float* out = (float*)d_out;

    zero_kernel<<<1, 1>>>();
    dim3 g1(WW / TILE, HH / TILE, 2 * BATCH);   // 8 x 8 x 32
    canny_state_kernel<<<g1, 256>>>(y_hat, y);
    dim3 g2(WW / TILE, HH / TILE, BATCH);       // 8 x 8 x 16
    hyst_count_kernel<<<g2, 256>>>();
    finalize_kernel<<<1, 1>>>(out);
}

// round 3
// speedup vs baseline: 1.3113x; 1.3113x over previous
#include <cuda_runtime.h>
#include <cstdint>

#define HH 512
#define WW 512
#define BATCH 16
#define WORDS 16  // 512 / 32
#define TILE 64
#define ST 76     // smem row stride in floats (odd float4 count -> conflict-free vertical f4)

// Scratch: bit-packed strong/weak masks for both inputs.
__device__ uint32_t g_strong[2 * BATCH * HH * WORDS];
__device__ uint32_t g_weak[2 * BATCH * HH * WORDS];
__device__ int g_cnt;
__device__ int g_done;

__device__ __forceinline__ int reflect_idx(int p, int n) {
    if (p < 0) p = -p;
    if (p >= n) p = 2 * n - 2 - p;
    return p;
}

// ---------------- Kernel 1: gray -> gaussian blur -> sobel+mag+bin -> NMS -> double threshold ----
// smem: A[72*76] floats, B[72*76] floats, bins[66*68] bytes  => ~47.2 KB (static)
__global__ __launch_bounds__(256) void canny_state_kernel(
    const float* __restrict__ in0, const float* __restrict__ in1)
{
    __shared__ float A[72 * ST];          // gray -> Bm (blur)
    __shared__ float Bsm[72 * ST];        // hblur -> mag
    __shared__ unsigned char bins[66 * 68];

    const int tx = blockIdx.x, ty = blockIdx.y, z = blockIdx.z;
    const int u = z >> 4, b = z & 15;
    const float* img = (u == 0 ? in0 : in1) + (size_t)b * 3 * HH * WW;
    const int TX = tx * TILE, TY = ty * TILE;
    const int tid = threadIdx.x;

    if (z == 0 && tx == 0 && ty == 0 && tid == 0) { g_cnt = 0; g_done = 0; }

    // Gaussian weights (sigma=1, 5 taps) — same formula as reference
    const float e2 = expf(-2.0f), e05 = expf(-0.5f);
    const float ssum = (((e2 + e05) + 1.0f) + e05) + e2;
    const float w0 = e2 / ssum, w1 = e05 / ssum, w2 = 1.0f / ssum;

    // ---- Phase 1: grayscale into A[72][ST], covering global rows TY-4..TY+67, cols TX-4..TX+67
    if (TX >= 4 && TX + 68 <= WW) {
        // interior-x: vectorized float4 path (rows still reflect-indexed)
        for (int t = tid; t < 72 * 18; t += 256) {
            int r = t / 18, c4 = t % 18;
            int rr = reflect_idx(TY - 4 + r, HH);
            const float* p = img + (size_t)rr * WW + (TX - 4) + 4 * c4;
            float4 rv = *(const float4*)p;
            float4 gv = *(const float4*)(p + HH * WW);
            float4 bv = *(const float4*)(p + 2 * HH * WW);
            float4 o;
            o.x = 0.299f * rv.x + 0.587f * gv.x + 0.114f * bv.x;
            o.y = 0.299f * rv.y + 0.587f * gv.y + 0.114f * bv.y;
            o.z = 0.299f * rv.z + 0.587f * gv.z + 0.114f * bv.z;
            o.w = 0.299f * rv.w + 0.587f * gv.w + 0.114f * bv.w;
            *(float4*)&A[r * ST + 4 * c4] = o;
        }
    } else {
        for (int t = tid; t < 72 * 72; t += 256) {
            int r = t / 72, c = t % 72;
            int rr = reflect_idx(TY - 4 + r, HH);
            int rc = reflect_idx(TX - 4 + c, WW);
            const float* p = img + (size_t)rr * WW + rc;
            A[r * ST + c] = 0.299f * p[0] + 0.587f * p[HH * WW] + 0.114f * p[2 * HH * WW];
        }
    }
    __syncthreads();

    // ---- Phase 2a: horizontal 5-tap blur. A(gray) -> Bsm(hblur), 72 rows x 68 cols
    for (int t = tid; t < 72 * 17; t += 256) {
        int r = t / 17, c4 = t % 17;
        float4 xa = *(const float4*)&A[r * ST + 4 * c4];
        float4 xb = *(const float4*)&A[r * ST + 4 * c4 + 4];
        float x0 = xa.x, x1 = xa.y, x2 = xa.z, x3 = xa.w;
        float x4 = xb.x, x5 = xb.y, x6 = xb.z, x7 = xb.w;
        float4 o;
        o.x = w0 * (x0 + x4) + w1 * (x1 + x3) + w2 * x2;
        o.y = w0 * (x1 + x5) + w1 * (x2 + x4) + w2 * x3;
        o.z = w0 * (x2 + x6) + w1 * (x3 + x5) + w2 * x4;
        o.w = w0 * (x3 + x7) + w1 * (x4 + x6) + w2 * x5;
        *(float4*)&Bsm[r * ST + 4 * c4] = o;
    }
    __syncthreads();

    // ---- Phase 2b: vertical 5-tap blur. Bsm(hblur) -> A(Bm), 68 rows x 68 cols, 4x4 register block
    for (int t = tid; t < 17 * 17; t += 256) {
        int rg = t / 17, c4 = t % 17;
        float4 y[8];
        #pragma unroll
        for (int k = 0; k < 8; k++) y[k] = *(const float4*)&Bsm[(4 * rg + k) * ST + 4 * c4];
        #pragma unroll
        for (int j = 0; j < 4; j++) {
            float4 o;
            o.x = w0 * (y[j].x + y[j + 4].x) + w1 * (y[j + 1].x + y[j + 3].x) + w2 * y[j + 2].x;
            o.y = w0 * (y[j].y + y[j + 4].y) + w1 * (y[j + 1].y + y[j + 3].y) + w2 * y[j + 2].y;
            o.z = w0 * (y[j].z + y[j + 4].z) + w1 * (y[j + 1].z + y[j + 3].z) + w2 * y[j + 2].z;
            o.w = w0 * (y[j].w + y[j + 4].w) + w1 * (y[j + 1].w + y[j + 3].w) + w2 * y[j + 2].w;
            *(float4*)&A[(4 * rg + j) * ST + 4 * c4] = o;
        }
    }
    __syncthreads();

    // ---- Phase 3: fused sobel + magnitude + direction bin. A(Bm) -> Bsm(mag), bins
    // mag[r][c] corresponds to global pixel (TY-1+r, TX-1+c), r,c in 0..65
    const float TAN22 = 0.41421356237309503f;  // tan(pi/8)
    for (int t = tid; t < 66 * 17; t += 256) {
        int r = t / 17, c4 = t % 17;
        float cs[3][4], cd[3][4];
        #pragma unroll
        for (int i = 0; i < 3; i++) {
            float4 xa = *(const float4*)&A[(r + i) * ST + 4 * c4];
            float4 xb = *(const float4*)&A[(r + i) * ST + 4 * c4 + 4];
            float x0 = xa.x, x1 = xa.y, x2 = xa.z, x3 = xa.w;
            float x4 = xb.x, x5 = xb.y, x6 = xb.z;
            cs[i][0] = x0 + 2.f * x1 + x2;  cd[i][0] = x2 - x0;
            cs[i][1] = x1 + 2.f * x2 + x3;  cd[i][1] = x3 - x1;
            cs[i][2] = x2 + 2.f * x3 + x4;  cd[i][2] = x4 - x2;
            cs[i][3] = x3 + 2.f * x4 + x5;  cd[i][3] = x5 - x3;
        }
        int gy_g0 = TY - 1 + r;
        bool row_ok = (gy_g0 >= 0) && (gy_g0 < HH);
        #pragma unroll
        for (int j = 0; j < 4; j++) {
            int c = 4 * c4 + j;
            if (c > 65) continue;
            float gxv = cd[0][j] + 2.f * cd[1][j] + cd[2][j];
            float gyv = cs[2][j] - cs[0][j];
            int gx_g = TX - 1 + c;
            float mag = 0.f;
            if (row_ok && gx_g >= 0 && gx_g < WW)
                mag = sqrtf(gxv * gxv + gyv * gyv + 1e-12f);
            int bin;
            float ax = fabsf(gxv), ay = fabsf(gyv);
            if (ay <= TAN22 * ax)      bin = 0;
            else if (ax <= TAN22 * ay) bin = 2;
            else bin = ((gxv > 0.f) == (gyv > 0.f)) ? 1 : 3;
            Bsm[r * ST + c] = mag;
            bins[r * 68 + c] = (unsigned char)bin;
        }
    }
    __syncthreads();

    // ---- Phase 4: NMS + double threshold, bit-pack via ballot
    const int wp = tid >> 5, l = tid & 31;
    for (int t = wp; t < 128; t += 8) {   // 64 rows x 2 column-segments
        int r = t >> 1, seg = t & 1;
        int c = seg * 32 + l;
        int mr = r + 1, mc = c + 1;       // mag coords
        int bin = bins[mr * 68 + mc];
        int dy = (bin == 0) ? 0 : 1;
        int dx = (bin == 2) ? 0 : ((bin == 3) ? -1 : 1);
        float magc = Bsm[mr * ST + mc];
        float n1 = Bsm[(mr + dy) * ST + (mc + dx)];
        float n2 = Bsm[(mr - dy) * ST + (mc - dx)];
        bool keep = (magc >= n1) && (magc >= n2);
        float nms = keep ? magc : 0.f;
        bool strong = (nms >= 0.2f);
        bool weak = (!strong) && (nms >= 0.1f);
        unsigned sm = __ballot_sync(0xffffffffu, strong);
        unsigned wm = __ballot_sync(0xffffffffu, weak);
        if (l == 0) {
            size_t idx = (((size_t)(u * BATCH + b) * HH) + (TY + r)) * WORDS + (tx * 2 + seg);
            g_strong[idx] = sm;
            g_weak[idx] = wm;
        }
    }
}

// ---------------- Kernel 2: 10x hysteresis (bitwise) + diff count + last-block finalize ----------
#define HR 84   // 64 + 2*10 rows halo
#define HW4 4   // 4 words = 128 bits (64 + 2*32 cols)

__global__ __launch_bounds__(256) void hyst_count_kernel(float* __restrict__ out)
{
    __shared__ uint32_t S[2][HR][HW4];
    __shared__ uint32_t Wk[2][HR][HW4];
    __shared__ uint32_t Hh[2][HR][HW4];
    __shared__ int warpsum[8];

    const int tx = blockIdx.x, ty = blockIdx.y, b = blockIdx.z;
    const int TY = ty * TILE;
    const int tid = threadIdx.x;
    const int NW = 2 * HR * HW4;  // 672

    for (int i = tid; i < NW; i += 256) {
        int uu = i / (HR * HW4);
        int rem = i % (HR * HW4);
        int r = rem / HW4, w = rem % HW4;
        int gy = TY - 10 + r;
        int gw = tx * 2 - 1 + w;
        uint32_t sv = 0, wv = 0;
        if (gy >= 0 && gy < HH && gw >= 0 && gw < WORDS) {
            size_t idx = (((size_t)(uu * BATCH + b) * HH) + gy) * WORDS + gw;
            sv = g_strong[idx];
            wv = g_weak[idx];
        }
        S[uu][r][w] = sv;
        Wk[uu][r][w] = wv;
    }
    __syncthreads();

    for (int it = 0; it < 10; it++) {
        for (int i = tid; i < NW; i += 256) {
            int uu = i / (HR * HW4);
            int rem = i % (HR * HW4);
            int r = rem / HW4, w = rem % HW4;
            uint32_t s = S[uu][r][w];
            uint32_t lf = (w > 0) ? S[uu][r][w - 1] : 0u;
            uint32_t rt = (w < HW4 - 1) ? S[uu][r][w + 1] : 0u;
            Hh[uu][r][w] = s | (s << 1) | (s >> 1) | (lf >> 31) | (rt << 31);
        }
        __syncthreads();
        for (int i = tid; i < NW; i += 256) {
            int uu = i / (HR * HW4);
            int rem = i % (HR * HW4);
            int r = rem / HW4, w = rem % HW4;
            uint32_t nb = Hh[uu][r][w];
            if (r > 0) nb |= Hh[uu][r - 1][w];
            if (r < HR - 1) nb |= Hh[uu][r + 1][w];
            uint32_t pr = Wk[uu][r][w] & nb;
            S[uu][r][w] |= pr;
            Wk[uu][r][w] &= ~pr;
        }
        __syncthreads();
    }

    // Count XOR popcount over 64x64 interior (rows 10..73, words 1..2)
    int cnt = 0;
    for (int i = tid; i < 128; i += 256) {
        int r = 10 + (i >> 1);
        int w = 1 + (i & 1);
        cnt += __popc(S[0][r][w] ^ S[1][r][w]);
    }
    #pragma unroll
    for (int off = 16; off; off >>= 1)
        cnt += __shfl_down_sync(0xffffffffu, cnt, off);
    if ((tid & 31) == 0) warpsum[tid >> 5] = cnt;
    __syncthreads();
    if (tid == 0) {
        int tot = 0;
        #pragma unroll
        for (int k = 0; k < 8; k++) tot += warpsum[k];
        atomicAdd(&g_cnt, tot);
        __threadfence();
        int ticket = atomicAdd(&g_done, 1);
        if (ticket == gridDim.x * gridDim.y * gridDim.z - 1) {
            int total = atomicAdd(&g_cnt, 0);
            out[0] = (float)total / 4194304.0f;  // 16*512*512
        }
    }
}

extern "C" void kernel_launch(void* const* d_in, const int* in_sizes, int n_in,
                              void* d_out, int out_size) {
    const float* y_hat = (const float*)d_in[0];
    const float* y     = (const float*)d_in[1];
    float* out = (float*)d_out;

    dim3 g1(WW / TILE, HH / TILE, 2 * BATCH);   // 8 x 8 x 32
    canny_state_kernel<<<g1, 256>>>(y_hat, y);
    dim3 g2(WW / TILE, HH / TILE, BATCH);       // 8 x 8 x 16
    hyst_count_kernel<<<g2, 256>>>(out);
}